// round 1
// baseline (speedup 1.0000x reference)
#include <cuda_runtime.h>
#include <math.h>

// Problem constants (fixed by the dataset episode config)
#define NS   5760      // total images = B*(WAY*SHOT+NQ)*P = 8*80*9
#define CO   640       // conv output channels
#define KD   192       // 3*8*8 reduction dim
#define NPOS 16        // 4x4 conv output positions
#define B_   8
#define WAY_ 5
#define NQ_  75
#define P_   9

// Scratch: normalized pooled feature vectors u[sample][channel]
__device__ float g_u[(size_t)NS * CO];

// ---------------------------------------------------------------------------
// Kernel 1: per-image conv GEMM + per-position channel L2-norm + avg-pool +
// final L2-norm over channels. One block per image (5760 blocks, 160 threads).
// Thread t owns channels {t, t+160, t+320, t+480}, all 16 positions.
// ---------------------------------------------------------------------------
__global__ void __launch_bounds__(160) k_conv(const float* __restrict__ data,
                                              const float* __restrict__ wgt) {
    __shared__ float xs[KD * NPOS];   // X rearranged [k][pos], 12 KB
    __shared__ float ssq[NPOS];       // per-position sum of squares over channels
    __shared__ float red[5];          // per-warp partials
    __shared__ float s_invn;

    const int s = blockIdx.x;
    const int t = threadIdx.x;
    const float* img = data + (size_t)s * 3072;   // [3,32,32] contiguous

    // Scatter raw image into xs[k*16+pos]. Each pixel maps to exactly one (k,pos).
    for (int i = t; i < 3072; i += 160) {
        float v = img[i];
        int ci  = i >> 10;
        int row = (i >> 5) & 31;
        int col = i & 31;
        int k   = ci * 64 + (row & 7) * 8 + (col & 7);
        int pos = (row >> 3) * 4 + (col >> 3);
        xs[k * NPOS + pos] = v;
    }
    if (t < NPOS) ssq[t] = 0.f;
    __syncthreads();

    float acc[4][NPOS];
#pragma unroll
    for (int c = 0; c < 4; c++)
#pragma unroll
        for (int p = 0; p < NPOS; p++) acc[c][p] = 0.f;

    const float* wr = wgt + (size_t)t * KD;

    for (int k = 0; k < KD; k += 4) {
        float4 wv[4];
#pragma unroll
        for (int c = 0; c < 4; c++)
            wv[c] = *reinterpret_cast<const float4*>(wr + (size_t)c * 160 * KD + k);
#pragma unroll
        for (int kk = 0; kk < 4; kk++) {
            const float* xr = &xs[(k + kk) * NPOS];
            float4 xa = *reinterpret_cast<const float4*>(xr + 0);
            float4 xb = *reinterpret_cast<const float4*>(xr + 4);
            float4 xc = *reinterpret_cast<const float4*>(xr + 8);
            float4 xd = *reinterpret_cast<const float4*>(xr + 12);
            float xv[NPOS] = {xa.x, xa.y, xa.z, xa.w, xb.x, xb.y, xb.z, xb.w,
                              xc.x, xc.y, xc.z, xc.w, xd.x, xd.y, xd.z, xd.w};
#pragma unroll
            for (int c = 0; c < 4; c++) {
                float wkc = (kk == 0) ? wv[c].x : (kk == 1) ? wv[c].y
                          : (kk == 2) ? wv[c].z : wv[c].w;
#pragma unroll
                for (int p = 0; p < NPOS; p++)
                    acc[c][p] = fmaf(wkc, xv[p], acc[c][p]);
            }
        }
    }

    // Per-position sum of squares over all 640 channels.
    const int lane = t & 31;
#pragma unroll
    for (int p = 0; p < NPOS; p++) {
        float v = acc[0][p] * acc[0][p] + acc[1][p] * acc[1][p]
                + acc[2][p] * acc[2][p] + acc[3][p] * acc[3][p];
#pragma unroll
        for (int off = 16; off; off >>= 1) v += __shfl_xor_sync(0xffffffffu, v, off);
        if (lane == 0) atomicAdd(&ssq[p], v);
    }
    __syncthreads();

    float inv[NPOS];
#pragma unroll
    for (int p = 0; p < NPOS; p++)
        inv[p] = 1.f / fmaxf(sqrtf(ssq[p]), 1e-12f);

    // v[c] = mean over positions of normalized feat; accumulate ||v||^2.
    float v4[4];
    float ss = 0.f;
#pragma unroll
    for (int c = 0; c < 4; c++) {
        float sum = 0.f;
#pragma unroll
        for (int p = 0; p < NPOS; p++) sum = fmaf(acc[c][p], inv[p], sum);
        v4[c] = sum * (1.f / 16.f);
        ss = fmaf(v4[c], v4[c], ss);
    }
#pragma unroll
    for (int off = 16; off; off >>= 1) ss += __shfl_xor_sync(0xffffffffu, ss, off);
    if (lane == 0) red[t >> 5] = ss;
    __syncthreads();
    if (t == 0) {
        float x = red[0] + red[1] + red[2] + red[3] + red[4];
        s_invn = 1.f / fmaxf(sqrtf(x), 1e-12f);
    }
    __syncthreads();
    float invn = s_invn;
#pragma unroll
    for (int c = 0; c < 4; c++)
        g_u[(size_t)s * CO + t + c * 160] = v4[c] * invn;
}

// ---------------------------------------------------------------------------
// Kernel 2: similarity matrices + greedy row/col pruning.
// One block per (b, query n): 600 blocks, 128 threads.
// ---------------------------------------------------------------------------
#define QSTRIDE 644   // 640 + 4 pad floats: rows shift 4 banks -> minimal conflicts

__global__ void __launch_bounds__(128) k_sim(float* __restrict__ out) {
    __shared__ float qsm[9 * QSTRIDE];
    __shared__ float ssm[9 * QSTRIDE];
    __shared__ float simm[81];

    const int b = blockIdx.x / NQ_;
    const int n = blockIdx.x % NQ_;
    const int t = threadIdx.x;

    // Load query patch vectors: u rows for sample (b*80 + 5 + n), patches 0..8
    const float* qb = g_u + ((size_t)(b * 80 + WAY_ + n) * P_) * CO;
    for (int i = t; i < 9 * 160; i += 128) {
        int r = i / 160, c4 = (i % 160) * 4;
        *reinterpret_cast<float4*>(&qsm[r * QSTRIDE + c4]) =
            *reinterpret_cast<const float4*>(qb + (size_t)r * CO + c4);
    }

    for (int m = 0; m < WAY_; m++) {
        const float* sb = g_u + ((size_t)(b * 80 + m) * P_) * CO;
        __syncthreads();   // previous iter's readers of ssm done; also covers qsm load
        for (int i = t; i < 9 * 160; i += 128) {
            int r = i / 160, c4 = (i % 160) * 4;
            *reinterpret_cast<float4*>(&ssm[r * QSTRIDE + c4]) =
                *reinterpret_cast<const float4*>(sb + (size_t)r * CO + c4);
        }
        __syncthreads();

        // sim[h][w] = <support patch h, query patch w>, h,w in 0..8
        if (t < 81) {
            const int h = t / 9, wq = t % 9;
            const float* sr = &ssm[h * QSTRIDE];
            const float* qr = &qsm[wq * QSTRIDE];
            float d = 0.f;
            for (int c = 0; c < CO; c += 4) {
                float4 a = *reinterpret_cast<const float4*>(sr + c);
                float4 q = *reinterpret_cast<const float4*>(qr + c);
                d = fmaf(a.x, q.x, d);
                d = fmaf(a.y, q.y, d);
                d = fmaf(a.z, q.z, d);
                d = fmaf(a.w, q.w, d);
            }
            simm[t] = d;
        }
        __syncthreads();

        // Greedy: 9 iterations of masked global argmax (first-index tie-break,
        // matching jnp.argmax), accumulate relu(max)*0.5^i, prune row+col.
        if (t < 32) {
            float v0 = simm[t];
            float v1 = simm[t + 32];
            float v2 = (t + 64 < 81) ? simm[t + 64] : -1e30f;
            unsigned rmask = 0x1FFu, cmask = 0x1FFu;
            float totalv = 0.f, beta = 1.f;
            for (int it = 0; it < 9; it++) {
                float bv = -1e30f;
                int bidx = 999;
                int j = t;
                if (((rmask >> (j / 9)) & 1) && ((cmask >> (j % 9)) & 1)) {
                    bv = v0; bidx = j;
                }
                j = t + 32;
                if (((rmask >> (j / 9)) & 1) && ((cmask >> (j % 9)) & 1)) {
                    if (v1 > bv || (v1 == bv && j < bidx)) { bv = v1; bidx = j; }
                }
                j = t + 64;
                if (j < 81 && ((rmask >> (j / 9)) & 1) && ((cmask >> (j % 9)) & 1)) {
                    if (v2 > bv || (v2 == bv && j < bidx)) { bv = v2; bidx = j; }
                }
#pragma unroll
                for (int off = 16; off; off >>= 1) {
                    float ov = __shfl_xor_sync(0xffffffffu, bv, off);
                    int   oi = __shfl_xor_sync(0xffffffffu, bidx, off);
                    if (ov > bv || (ov == bv && oi < bidx)) { bv = ov; bidx = oi; }
                }
                totalv = fmaf(fmaxf(bv, 0.f), beta, totalv);
                beta *= 0.5f;
                rmask &= ~(1u << (bidx / 9));
                cmask &= ~(1u << (bidx % 9));
            }
            // output layout [b, N, M]
            if (t == 0) out[((size_t)b * NQ_ + n) * WAY_ + m] = totalv;
        }
    }
}

// ---------------------------------------------------------------------------
extern "C" void kernel_launch(void* const* d_in, const int* in_sizes, int n_in,
                              void* d_out, int out_size) {
    const float* data   = (const float*)d_in[0];   // [640, 9, 3, 32, 32] fp32
    const float* conv_w = (const float*)d_in[1];   // [640, 3, 8, 8] fp32
    (void)in_sizes; (void)n_in; (void)out_size;

    k_conv<<<NS, 160>>>(data, conv_w);
    k_sim<<<B_ * NQ_, 128>>>((float*)d_out);
}